// round 2
// baseline (speedup 1.0000x reference)
#include <cuda_runtime.h>
#include <math.h>

#define BB 2
#define LL 1024
#define DD 1024
#define NN 16
#define RR 64

// scratch (no device allocations allowed)
__device__ float g_tmp[BB * LL * RR];
__device__ float g_delta[BB * LL * DD];
__device__ float g_Bt[BB * LL * NN];
__device__ float g_Ct[BB * LL * NN];

// ---------------- tiled SGEMM (projections) ----------------
#define BM 64
#define BN 64
#define BK 16

__global__ void __launch_bounds__(256) sgemm_k(
    const float* __restrict__ A, const float* __restrict__ B,
    float* __restrict__ C, int M, int N, int K, int epi)
{
    __shared__ float As[BK][BM + 1];
    __shared__ float Bs[BK][BN];
    int tid = threadIdx.x;
    int m0 = blockIdx.y * BM;
    int n0 = blockIdx.x * BN;
    float acc[4][4];
#pragma unroll
    for (int i = 0; i < 4; i++)
#pragma unroll
        for (int j = 0; j < 4; j++) acc[i][j] = 0.f;
    int tr = tid >> 4, tc = tid & 15;

    for (int k0 = 0; k0 < K; k0 += BK) {
        for (int i = tid; i < BM * BK; i += 256) {
            int m = i / BK, k = i % BK;
            int gm = m0 + m, gk = k0 + k;
            As[k][m] = (gm < M && gk < K) ? A[(size_t)gm * K + gk] : 0.f;
        }
        for (int i = tid; i < BK * BN; i += 256) {
            int k = i / BN, n = i % BN;
            int gk = k0 + k, gn = n0 + n;
            Bs[k][n] = (gk < K && gn < N) ? B[(size_t)gk * N + gn] : 0.f;
        }
        __syncthreads();
#pragma unroll
        for (int k = 0; k < BK; ++k) {
            float a[4], b[4];
#pragma unroll
            for (int i = 0; i < 4; i++) a[i] = As[k][tr * 4 + i];
#pragma unroll
            for (int j = 0; j < 4; j++) b[j] = Bs[k][tc * 4 + j];
#pragma unroll
            for (int i = 0; i < 4; i++)
#pragma unroll
                for (int j = 0; j < 4; j++)
                    acc[i][j] = fmaf(a[i], b[j], acc[i][j]);
        }
        __syncthreads();
    }

#pragma unroll
    for (int i = 0; i < 4; i++) {
        int gm = m0 + tr * 4 + i;
        if (gm >= M) continue;
#pragma unroll
        for (int j = 0; j < 4; j++) {
            int gn = n0 + tc * 4 + j;
            if (gn >= N) continue;
            float v = acc[i][j];
            if (epi) {
                // softplus = max(v,0) + log1p(exp(-|v|))  (== jax.nn.softplus)
                v = fmaxf(v, 0.f) + log1pf(expf(-fabsf(v)));
            }
            C[(size_t)gm * N + gn] = v;
        }
    }
}

// ---------------- sequential resonance scan (op-for-op faithful) ----------------
// One thread per (b, d, n). 16-lane groups share (b, d), vary n.
// Mirrors the reference's polar round-trips literally:
//   c_mag(z)   = sqrt(zx*zx + zy*zy + 1e-8)
//   c_phase(z) = atan2(zy, zx + 1e-10)
//   c_from_polar(m, p) = (m*cos p, m*sin p)
// All recurrence arithmetic uses __f*_rn intrinsics to block fma contraction
// (matches the reference's mul/mul/add/add evaluation order).
__global__ void __launch_bounds__(256) scan_k(
    const float* __restrict__ x, const float* __restrict__ A_log,
    const float* __restrict__ Dskip, float* __restrict__ y)
{
    int tid = threadIdx.x;
    int bid = blockIdx.x;                 // 0..127
    int b = bid >> 6;                     // 0..1
    int d = ((bid & 63) << 4) | (tid >> 4);
    int n = tid & 15;

    float An = expf(A_log[n]);
    // phases = linspace(0, 2*pi*(1-1/16), 16): step = 2*pi/16
    float phi = (float)n * 0.39269908169872414f;
    float sphi, cphi;
    sincosf(phi, &sphi, &cphi);
    float hx = __fmul_rn(0.01f, cphi), hy = __fmul_rn(0.01f, sphi);
    float dsk = Dskip[d];

    size_t rowbase = ((size_t)b * LL) * DD + d;
    const float* xp = x + rowbase;
    const float* dp = g_delta + rowbase;
    const float* bp = g_Bt + ((size_t)b * LL) * NN + n;
    const float* cp = g_Ct + ((size_t)b * LL) * NN + n;
    float* yp = y + rowbase;

    float xv = __ldg(xp);
    float dv = __ldg(dp);
    float bn = __ldg(bp);
    float cn = __ldg(cp);

#pragma unroll 1
    for (int t = 0; t < LL; ++t) {
        // software-pipelined loads for t+1
        int tn = (t < LL - 1) ? (t + 1) : t;
        float xv2 = __ldg(xp + (size_t)tn * DD);
        float dv2 = __ldg(dp + (size_t)tn * DD);
        float bn2 = __ldg(bp + tn * NN);
        float cn2 = __ldg(cp + tn * NN);

        // ---- fractal_compress(h, e) ----
        float mag = __fsqrt_rn(__fadd_rn(__fadd_rn(__fmul_rn(hx, hx), __fmul_rn(hy, hy)), 1e-8f));
        float ph  = atan2f(hy, __fadd_rn(hx, 1e-10f));
        float e   = __fadd_rn(1.0f, __fmul_rn(dv, An));
        float cm  = fminf(expf(__fmul_rn(e, logf(__fadd_rn(mag, 1e-8f)))), 10.0f);
        float sph, cph;
        sincosf(ph, &sph, &cph);
        float hcx = __fmul_rn(cm, cph);
        float hcy = __fmul_rn(cm, sph);

        // ---- injection on carrier phases ----
        float u   = __fmul_rn(xv, bn);
        float ijx = __fmul_rn(u, cphi);
        float ijy = __fmul_rn(u, sphi);

        // ---- resonance gate: gamma = 0.5 * cos((pa-pb)/2)^2 ----
        float pa = atan2f(ijy, __fadd_rn(ijx, 1e-10f));
        float pb = atan2f(hcy, __fadd_rn(hcx, 1e-10f));
        float cd = cosf(__fmul_rn(__fsub_rn(pa, pb), 0.5f));
        float gam = __fmul_rn(0.5f, __fmul_rn(cd, cd));

        // ---- inject + mag_squash ----
        float sx = __fadd_rn(hcx, __fmul_rn(gam, ijx));
        float sy = __fadd_rn(hcy, __fmul_rn(gam, ijy));
        float sm = __fsqrt_rn(__fadd_rn(__fadd_rn(__fmul_rn(sx, sx), __fmul_rn(sy, sy)), 1e-8f));
        float ps = atan2f(sy, __fadd_rn(sx, 1e-10f));
        float th = tanhf(sm);
        float sps, cps;
        sincosf(ps, &sps, &cps);
        hx = __fmul_rn(th, cps);
        hy = __fmul_rn(th, sps);

        // ---- readout: sum_n hx * C_n over the 16-lane group ----
        float v = __fmul_rn(hx, cn);
        v += __shfl_xor_sync(0xffffffffu, v, 8);
        v += __shfl_xor_sync(0xffffffffu, v, 4);
        v += __shfl_xor_sync(0xffffffffu, v, 2);
        v += __shfl_xor_sync(0xffffffffu, v, 1);
        if (n == 0) yp[(size_t)t * DD] = __fadd_rn(__fmul_rn(xv, dsk), v);

        xv = xv2; dv = dv2; bn = bn2; cn = cn2;
    }
}

extern "C" void kernel_launch(void* const* d_in, const int* in_sizes, int n_in,
                              void* d_out, int out_size)
{
    // Defensive input resolution by element count (dict order is the tiebreak
    // for same-size pairs, matching metadata.txt insertion order).
    const float *x = 0, *A_log = 0, *W_dt1 = 0, *W_dt2 = 0, *W_B = 0, *W_C = 0, *Dskip = 0;
    for (int i = 0; i < n_in; ++i) {
        const float* p = (const float*)d_in[i];
        int s = in_sizes[i];
        if (s == BB * LL * DD)      { if (!x) x = p; }
        else if (s == NN)           { if (!A_log) A_log = p; }
        else if (s == DD * RR)      { if (!W_dt1) W_dt1 = p; else W_dt2 = p; }
        else if (s == DD * NN)      { if (!W_B) W_B = p; else W_C = p; }
        else if (s == DD)           { if (!Dskip) Dskip = p; }
    }
    float* y = (float*)d_out;

    float *tmp, *delta, *bt, *ct;
    cudaGetSymbolAddress((void**)&tmp,   g_tmp);
    cudaGetSymbolAddress((void**)&delta, g_delta);
    cudaGetSymbolAddress((void**)&bt,    g_Bt);
    cudaGetSymbolAddress((void**)&ct,    g_Ct);

    const int M = BB * LL;  // 2048
    // tmp = x @ W_dt1                  (2048 x 64, K=1024)
    sgemm_k<<<dim3((RR + BN - 1) / BN, (M + BM - 1) / BM), 256>>>(x, W_dt1, tmp, M, RR, DD, 0);
    // delta = softplus(tmp @ W_dt2)    (2048 x 1024, K=64)
    sgemm_k<<<dim3((DD + BN - 1) / BN, (M + BM - 1) / BM), 256>>>(tmp, W_dt2, delta, M, DD, RR, 1);
    // Bt = x @ W_B                     (2048 x 16, K=1024)
    sgemm_k<<<dim3((NN + BN - 1) / BN, (M + BM - 1) / BM), 256>>>(x, W_B, bt, M, NN, DD, 0);
    // Ct = x @ W_C
    sgemm_k<<<dim3((NN + BN - 1) / BN, (M + BM - 1) / BM), 256>>>(x, W_C, ct, M, NN, DD, 0);
    // sequential scan + readout + skip
    scan_k<<<128, 256>>>(x, A_log, Dskip, y);
}

// round 3
// speedup vs baseline: 1.2176x; 1.2176x over previous
#include <cuda_runtime.h>
#include <math.h>

#define BB 2
#define LL 1024
#define DD 1024
#define NN 16
#define RR 64

// scratch (no device allocations allowed)
__device__ float g_tmp[BB * LL * RR];
__device__ float g_delta[BB * LL * DD];
__device__ float g_Bt[BB * LL * NN];
__device__ float g_Ct[BB * LL * NN];

// ---------------- skinny GEMM: C[M,N] = A[M,K] @ W[K,N] ----------------
// Thread-per-output, strictly sequential k-ascending fmaf chain
// => bit-identical accumulation to the previous sgemm_k.
template <int N_, int TM, int CK>
__global__ void __launch_bounds__(256) skinny_gemm(
    const float* __restrict__ A, const float* __restrict__ W,
    float* __restrict__ C, int M, int K)
{
    __shared__ float As[TM][CK];
    __shared__ float Ws[CK][N_];
    int tid = threadIdx.x;
    int m0 = blockIdx.x * TM;
    int r = tid / N_;
    int n = tid % N_;
    float acc = 0.f;

    for (int k0 = 0; k0 < K; k0 += CK) {
        __syncthreads();
        for (int i = tid; i < TM * CK; i += 256) {
            int rr = i / CK, kk = i % CK;
            As[rr][kk] = A[(size_t)(m0 + rr) * K + (k0 + kk)];
        }
        for (int i = tid; i < CK * N_; i += 256) {
            int kk = i / N_, nn = i % N_;
            Ws[kk][nn] = W[(size_t)(k0 + kk) * N_ + nn];
        }
        __syncthreads();
#pragma unroll
        for (int k = 0; k < CK; ++k)
            acc = fmaf(As[r][k], Ws[k][n], acc);
    }
    C[(size_t)(m0 + r) * N_ + n] = acc;
}

// ---------------- delta GEMM + softplus ----------------
// C[2048,1024] = softplus(T[2048,64] @ W[64,1024]); sequential k fmaf chain,
// identical epilogue formula => bit-identical to previous sgemm_k epi path.
__global__ void __launch_bounds__(256) delta_gemm(
    const float* __restrict__ T, const float* __restrict__ W,
    float* __restrict__ C)
{
    __shared__ float ts[8][64];
    int tid = threadIdx.x;
    int m0 = blockIdx.y * 8;
    int n  = blockIdx.x * 256 + tid;

    for (int i = tid; i < 8 * 64; i += 256)
        ts[i / 64][i % 64] = T[(size_t)(m0 + i / 64) * 64 + (i % 64)];
    __syncthreads();

    float acc[8];
#pragma unroll
    for (int r = 0; r < 8; ++r) acc[r] = 0.f;

#pragma unroll
    for (int k = 0; k < 64; ++k) {
        float w = W[(size_t)k * 1024 + n];
#pragma unroll
        for (int r = 0; r < 8; ++r)
            acc[r] = fmaf(ts[r][k], w, acc[r]);
    }

#pragma unroll
    for (int r = 0; r < 8; ++r) {
        float v = acc[r];
        // softplus = max(v,0) + log1p(exp(-|v|))  (== jax.nn.softplus)
        v = fmaxf(v, 0.f) + log1pf(expf(-fabsf(v)));
        C[(size_t)(m0 + r) * 1024 + n] = v;
    }
}

// ---------------- sequential resonance scan (op-for-op faithful) ----------------
// UNCHANGED from the passing R2 kernel — numerics are chaotic-sensitive.
__global__ void __launch_bounds__(256) scan_k(
    const float* __restrict__ x, const float* __restrict__ A_log,
    const float* __restrict__ Dskip, float* __restrict__ y)
{
    int tid = threadIdx.x;
    int bid = blockIdx.x;                 // 0..127
    int b = bid >> 6;                     // 0..1
    int d = ((bid & 63) << 4) | (tid >> 4);
    int n = tid & 15;

    float An = expf(A_log[n]);
    float phi = (float)n * 0.39269908169872414f;
    float sphi, cphi;
    sincosf(phi, &sphi, &cphi);
    float hx = __fmul_rn(0.01f, cphi), hy = __fmul_rn(0.01f, sphi);
    float dsk = Dskip[d];

    size_t rowbase = ((size_t)b * LL) * DD + d;
    const float* xp = x + rowbase;
    const float* dp = g_delta + rowbase;
    const float* bp = g_Bt + ((size_t)b * LL) * NN + n;
    const float* cp = g_Ct + ((size_t)b * LL) * NN + n;
    float* yp = y + rowbase;

    float xv = __ldg(xp);
    float dv = __ldg(dp);
    float bn = __ldg(bp);
    float cn = __ldg(cp);

#pragma unroll 1
    for (int t = 0; t < LL; ++t) {
        int tn = (t < LL - 1) ? (t + 1) : t;
        float xv2 = __ldg(xp + (size_t)tn * DD);
        float dv2 = __ldg(dp + (size_t)tn * DD);
        float bn2 = __ldg(bp + tn * NN);
        float cn2 = __ldg(cp + tn * NN);

        // ---- fractal_compress(h, e) ----
        float mag = __fsqrt_rn(__fadd_rn(__fadd_rn(__fmul_rn(hx, hx), __fmul_rn(hy, hy)), 1e-8f));
        float ph  = atan2f(hy, __fadd_rn(hx, 1e-10f));
        float e   = __fadd_rn(1.0f, __fmul_rn(dv, An));
        float cm  = fminf(expf(__fmul_rn(e, logf(__fadd_rn(mag, 1e-8f)))), 10.0f);
        float sph, cph;
        sincosf(ph, &sph, &cph);
        float hcx = __fmul_rn(cm, cph);
        float hcy = __fmul_rn(cm, sph);

        // ---- injection on carrier phases ----
        float u   = __fmul_rn(xv, bn);
        float ijx = __fmul_rn(u, cphi);
        float ijy = __fmul_rn(u, sphi);

        // ---- resonance gate: gamma = 0.5 * cos((pa-pb)/2)^2 ----
        float pa = atan2f(ijy, __fadd_rn(ijx, 1e-10f));
        float pb = atan2f(hcy, __fadd_rn(hcx, 1e-10f));
        float cd = cosf(__fmul_rn(__fsub_rn(pa, pb), 0.5f));
        float gam = __fmul_rn(0.5f, __fmul_rn(cd, cd));

        // ---- inject + mag_squash ----
        float sx = __fadd_rn(hcx, __fmul_rn(gam, ijx));
        float sy = __fadd_rn(hcy, __fmul_rn(gam, ijy));
        float sm = __fsqrt_rn(__fadd_rn(__fadd_rn(__fmul_rn(sx, sx), __fmul_rn(sy, sy)), 1e-8f));
        float ps = atan2f(sy, __fadd_rn(sx, 1e-10f));
        float th = tanhf(sm);
        float sps, cps;
        sincosf(ps, &sps, &cps);
        hx = __fmul_rn(th, cps);
        hy = __fmul_rn(th, sps);

        // ---- readout ----
        float v = __fmul_rn(hx, cn);
        v += __shfl_xor_sync(0xffffffffu, v, 8);
        v += __shfl_xor_sync(0xffffffffu, v, 4);
        v += __shfl_xor_sync(0xffffffffu, v, 2);
        v += __shfl_xor_sync(0xffffffffu, v, 1);
        if (n == 0) yp[(size_t)t * DD] = __fadd_rn(__fmul_rn(xv, dsk), v);

        xv = xv2; dv = dv2; bn = bn2; cn = cn2;
    }
}

extern "C" void kernel_launch(void* const* d_in, const int* in_sizes, int n_in,
                              void* d_out, int out_size)
{
    const float *x = 0, *A_log = 0, *W_dt1 = 0, *W_dt2 = 0, *W_B = 0, *W_C = 0, *Dskip = 0;
    for (int i = 0; i < n_in; ++i) {
        const float* p = (const float*)d_in[i];
        int s = in_sizes[i];
        if (s == BB * LL * DD)      { if (!x) x = p; }
        else if (s == NN)           { if (!A_log) A_log = p; }
        else if (s == DD * RR)      { if (!W_dt1) W_dt1 = p; else W_dt2 = p; }
        else if (s == DD * NN)      { if (!W_B) W_B = p; else W_C = p; }
        else if (s == DD)           { if (!Dskip) Dskip = p; }
    }
    float* y = (float*)d_out;

    float *tmp, *delta, *bt, *ct;
    cudaGetSymbolAddress((void**)&tmp,   g_tmp);
    cudaGetSymbolAddress((void**)&delta, g_delta);
    cudaGetSymbolAddress((void**)&bt,    g_Bt);
    cudaGetSymbolAddress((void**)&ct,    g_Ct);

    const int M = BB * LL;  // 2048
    // tmp = x @ W_dt1      (2048 x 64, K=1024): 4 rows/block -> 512 blocks
    skinny_gemm<64, 4, 64><<<M / 4, 256>>>(x, W_dt1, tmp, M, DD);
    // delta = softplus(tmp @ W_dt2)  (2048 x 1024, K=64): 1024 blocks
    delta_gemm<<<dim3(4, M / 8), 256>>>(tmp, W_dt2, delta);
    // Bt = x @ W_B         (2048 x 16, K=1024): 16 rows/block -> 128 blocks
    skinny_gemm<16, 16, 64><<<M / 16, 256>>>(x, W_B, bt, M, DD);
    // Ct = x @ W_C
    skinny_gemm<16, 16, 64><<<M / 16, 256>>>(x, W_C, ct, M, DD);
    // sequential scan + readout + skip (numerically untouched)
    scan_k<<<128, 256>>>(x, A_log, Dskip, y);
}